// round 8
// baseline (speedup 1.0000x reference)
#include <cuda_runtime.h>

#define NJ    24
#define BATCH 500000
#define QUADS (BATCH/4)        // 125000 threads, 4 batch rows each
#define TPB   128
#define WPJ   104              // floats per joint: 13 row-chunks x 8 {bias,w0..w6}
#define SW_N  (NJ*WPJ)         // 2496 floats = 9984 B static smem

__global__ __launch_bounds__(TPB, 2)
void se1d_kernel(const float* __restrict__ x,
                 const float* __restrict__ W1, const float* __restrict__ b1,
                 const float* __restrict__ W2, const float* __restrict__ b2,
                 float* __restrict__ out)
{
    // Scalar (non-duplicated) weights in smem, consumption order.
    // Per joint j: 13 chunks of 8 floats, each 32B-aligned:
    //   chunks 0..6 :  {b1[r],   W1[r][0..6]}
    //   chunks 7..12:  {b2[r-7], W2[r-7][0..6]}
    __shared__ __align__(16) float sw[SW_N];
    for (int idx = threadIdx.x; idx < SW_N; idx += TPB) {
        int j = idx / WPJ, o = idx - j * WPJ;
        int row = o >> 3, s = o & 7;
        float v;
        if (row < 7) v = (s == 0) ? b1[j*7 + row]     : W1[j*49 + row*7     + (s-1)];
        else         v = (s == 0) ? b2[j*6 + (row-7)] : W2[j*42 + (row-7)*7 + (s-1)];
        sw[idx] = v;
    }
    __syncthreads();

    const int t = blockIdx.x * TPB + threadIdx.x;
    if (t >= QUADS) return;

    const float4* xr = (const float4*)(x + (long)t * 96);  // 4 rows x 24 floats
    float* ob = out + (long)t * 576;                       // 4 rows x 144 floats

    float f[4][NJ][6];   // literal indices only -> SROA'd; max ~3 joints live
    float xc[4][4];      // current 4-joint x chunk, per row
    float h[4][7];

// Load x chunk q (joints 4q..4q+3) for all 4 rows.
#define LOADX(q) do { \
    _Pragma("unroll") \
    for (int R = 0; R < 4; R++) { \
        float4 v_ = xr[R*6 + (q)]; \
        xc[R][0] = v_.x; xc[R][1] = v_.y; xc[R][2] = v_.z; xc[R][3] = v_.w; \
    } \
} while (0)

// One joint: L1 (7x7) + L2 (6x7), 4 rows sharing each weight register.
#define JOINT(j, HAS_P, p) do { \
    const float* wj_ = sw + (j)*WPJ; \
    _Pragma("unroll") \
    for (int r = 0; r < 7; r++) { \
        const float4* c_ = (const float4*)(wj_ + r*8); \
        float4 qa_ = c_[0]; \
        float4 qb_; \
        if (HAS_P) qb_ = c_[1]; \
        _Pragma("unroll") \
        for (int R = 0; R < 4; R++) { \
            float a_ = fmaf(qa_.y, xc[R][(j)&3], qa_.x); \
            if (HAS_P) { \
                a_ = fmaf(qa_.z, f[R][p][0], a_); \
                a_ = fmaf(qa_.w, f[R][p][1], a_); \
                a_ = fmaf(qb_.x, f[R][p][2], a_); \
                a_ = fmaf(qb_.y, f[R][p][3], a_); \
                a_ = fmaf(qb_.z, f[R][p][4], a_); \
                a_ = fmaf(qb_.w, f[R][p][5], a_); \
            } \
            h[R][r] = fmaxf(a_, 0.f); \
        } \
    } \
    _Pragma("unroll") \
    for (int r = 0; r < 6; r++) { \
        const float4* c_ = (const float4*)(wj_ + (7+r)*8); \
        float4 qa_ = c_[0], qb_ = c_[1]; \
        _Pragma("unroll") \
        for (int R = 0; R < 4; R++) { \
            float a_ = fmaf(qa_.y, h[R][0], qa_.x); \
            a_ = fmaf(qa_.z, h[R][1], a_); \
            a_ = fmaf(qa_.w, h[R][2], a_); \
            a_ = fmaf(qb_.x, h[R][3], a_); \
            a_ = fmaf(qb_.y, h[R][4], a_); \
            a_ = fmaf(qb_.z, h[R][5], a_); \
            a_ = fmaf(qb_.w, h[R][6], a_); \
            f[R][j][r] = fmaxf(a_, 0.f); \
        } \
    } \
} while (0)

// Flush joints (j-1, j): 12 floats/row = 3 aligned STG.128, straight from feat regs.
#define FLUSH(j) do { \
    _Pragma("unroll") \
    for (int R = 0; R < 4; R++) { \
        float* o_ = ob + R*144 + ((j)-1)*6; \
        *(float4*)(o_+0) = make_float4(f[R][(j)-1][0], f[R][(j)-1][1], f[R][(j)-1][2], f[R][(j)-1][3]); \
        *(float4*)(o_+4) = make_float4(f[R][(j)-1][4], f[R][(j)-1][5], f[R][(j)][0],   f[R][(j)][1]); \
        *(float4*)(o_+8) = make_float4(f[R][(j)][2],   f[R][(j)][3],   f[R][(j)][4],   f[R][(j)][5]); \
    } \
} while (0)

    // Topological order 0..23 (PARENTS[i] < i), parents as literals.
    LOADX(0);
    JOINT(0, 0, 0);   JOINT(1, 1, 0);   FLUSH(1);
    JOINT(2, 1, 0);   JOINT(3, 1, 0);   FLUSH(3);
    LOADX(1);
    JOINT(4, 1, 1);   JOINT(5, 1, 2);   FLUSH(5);
    JOINT(6, 1, 3);   JOINT(7, 1, 4);   FLUSH(7);
    LOADX(2);
    JOINT(8, 1, 5);   JOINT(9, 1, 6);   FLUSH(9);
    JOINT(10, 1, 7);  JOINT(11, 1, 8);  FLUSH(11);
    LOADX(3);
    JOINT(12, 1, 9);  JOINT(13, 1, 9);  FLUSH(13);
    JOINT(14, 1, 9);  JOINT(15, 1, 12); FLUSH(15);
    LOADX(4);
    JOINT(16, 1, 13); JOINT(17, 1, 14); FLUSH(17);
    JOINT(18, 1, 16); JOINT(19, 1, 17); FLUSH(19);
    LOADX(5);
    JOINT(20, 1, 18); JOINT(21, 1, 19); FLUSH(21);
    JOINT(22, 1, 20); JOINT(23, 1, 21); FLUSH(23);
}

extern "C" void kernel_launch(void* const* d_in, const int* in_sizes, int n_in,
                              void* d_out, int out_size)
{
    const float* x  = (const float*)d_in[0];
    const float* W1 = (const float*)d_in[1];
    const float* b1 = (const float*)d_in[2];
    const float* W2 = (const float*)d_in[3];
    const float* b2 = (const float*)d_in[4];
    float* out = (float*)d_out;

    const int blocks = (QUADS + TPB - 1) / TPB;
    se1d_kernel<<<blocks, TPB>>>(x, W1, b1, W2, b2, out);
}